// round 4
// baseline (speedup 1.0000x reference)
#include <cuda_runtime.h>
#include <cstdint>

#define BQ   2
#define SEQ  2048
#define DIMC 1024
#define NH   16
#define DH   64
#define QKVC 3072
#define NROWS (BQ*SEQ)

// ---- device scratch ----
__device__ float g_xn[(size_t)NROWS * DIMC];            // 16 MB   tf32-rounded LN out
__device__ float g_qkv[(size_t)NROWS * QKVC];           // 48 MB   [q*0.125 | k | v], tf32-rounded
__device__ float g_dots[(size_t)BQ * NH * SEQ * SEQ];   // 512 MB  dots, then probs (probs tf32-rounded)
__device__ float g_ao[(size_t)BQ * NH * SEQ * DH];      // 16 MB   [b,g,i,d], tf32-rounded
__device__ float g_wqt[(size_t)DIMC * DIMC];            // 4 MB    Wq^T  [n][k], rounded
__device__ float g_wkvt[(size_t)2 * DIMC * DIMC];       // 8 MB    Wkv^T [n][k], rounded
__device__ float g_woutt[(size_t)DIMC * DIMC];          // 4 MB    Wout^T[n][k], rounded
__device__ float g_vt[(size_t)BQ * NH * DH * SEQ];      // 16 MB   V^T per (b,g): [d][j], rounded

__device__ __forceinline__ float tf32r(float x) {
    uint32_t u; asm("cvt.rna.tf32.f32 %0, %1;" : "=r"(u) : "f"(x));
    return __uint_as_float(u);
}

#define MMA_TF32(c, a, b) \
    asm volatile("mma.sync.aligned.m16n8k8.row.col.f32.tf32.tf32.f32 " \
        "{%0,%1,%2,%3}, {%4,%5,%6,%7}, {%8,%9}, {%0,%1,%2,%3};" \
        : "+f"((c)[0]), "+f"((c)[1]), "+f"((c)[2]), "+f"((c)[3]) \
        : "r"((a)[0]), "r"((a)[1]), "r"((a)[2]), "r"((a)[3]), \
          "r"((b)[0]), "r"((b)[1]))

// XOR-swizzled word index inside a [rows][32] f32 tile (conflict-free frags)
#define WIDX(m,k) (((m)*32) + (((((k)>>2)&7)^((m)&7))<<2) + ((k)&3))

// ============================================================ GEMM engine
// C[128 x BN] = A[128 x 32*KB] @ Bt[BN x 32*KB]^T   (Bt rows are n, cols k)
// 256 threads, BK=32, 2-stage smem double buffer, register prefetch.
template<int BN, int MT, bool APL>
__device__ __forceinline__ void gemm_core(
    const float* __restrict__ A, int lda, int aplane,
    const float* __restrict__ Bt, int ldb,
    float* __restrict__ C, int ldc, int KB,
    float cscale, int doRound, const float* __restrict__ bias)
{
    extern __shared__ float sm[];
    constexpr int ASZ = 128 * 32;
    constexpr int BSZ = BN * 32;
    constexpr int NT  = 4;
    constexpr int BCH = (BN == 128) ? 4 : 2;
    constexpr int BST = (BN == 128) ? 8 : 16;   // k stride between B chunks

    int t = threadIdx.x, lane = t & 31, w = t >> 5;
    int wm = (BN == 128) ? (w & 1) * 64 : (w & 3) * 32;
    int wn = (BN == 128) ? (w >> 1) * 32 : (w >> 2) * 32;

    int am = t >> 1,                 ak = (t & 1) * 4;              // A chunks: k = ak + c*8
    int bn_ = (BN == 128) ? (t >> 1) : (t >> 2);
    int bk  = (BN == 128) ? (t & 1) * 4 : (t & 3) * 4;              // B chunks: k = bk + c*BST

    const float* Arow = A + (size_t)am * lda;
    const float* Brow = Bt + (size_t)bn_ * ldb;

    float4 aR[4], bR[BCH];
    float acc[MT][NT][4];
    #pragma unroll
    for (int mt = 0; mt < MT; mt++)
        #pragma unroll
        for (int nt = 0; nt < NT; nt++)
            #pragma unroll
            for (int i = 0; i < 4; i++) acc[mt][nt][i] = 0.f;

    // ---- prologue: load k-block 0, stage 0 ----
    {
        #pragma unroll
        for (int c = 0; c < 4; c++) {
            int k = ak + c * 8;
            size_t off = APL ? ((size_t)(k >> 6) * aplane + (k & 63)) : (size_t)k;
            aR[c] = *(const float4*)(Arow + off);
        }
        #pragma unroll
        for (int c = 0; c < BCH; c++) {
            int k = bk + c * BST;
            bR[c] = *(const float4*)(Brow + k);
        }
        float* sA = sm;
        float* sB = sm + ASZ;
        #pragma unroll
        for (int c = 0; c < 4; c++) {
            int k = ak + c * 8;
            *(float4*)&sA[(am * 32) + (((((k >> 2) & 7) ^ (am & 7))) << 2)] = aR[c];
        }
        #pragma unroll
        for (int c = 0; c < BCH; c++) {
            int k = bk + c * BST;
            *(float4*)&sB[(bn_ * 32) + (((((k >> 2) & 7) ^ (bn_ & 7))) << 2)] = bR[c];
        }
    }
    __syncthreads();

    int stage = 0;
    int lm = lane >> 2, lk = lane & 3;
    for (int kb = 0; kb < KB; kb++) {
        bool more = (kb + 1 < KB);
        if (more) {
            int kbase = (kb + 1) * 32;
            #pragma unroll
            for (int c = 0; c < 4; c++) {
                int k = kbase + ak + c * 8;
                size_t off = APL ? ((size_t)(k >> 6) * aplane + (k & 63)) : (size_t)k;
                aR[c] = *(const float4*)(Arow + off);
            }
            #pragma unroll
            for (int c = 0; c < BCH; c++) {
                int k = kbase + bk + c * BST;
                bR[c] = *(const float4*)(Brow + k);
            }
        }
        const float* sA = sm + stage * (ASZ + BSZ);
        const float* sB = sA + ASZ;
        #pragma unroll
        for (int ks = 0; ks < 4; ks++) {
            int k0 = ks * 8 + lk;
            uint32_t af[MT][4], bf[NT][2];
            #pragma unroll
            for (int mt = 0; mt < MT; mt++) {
                int m1 = wm + mt * 16 + lm;
                af[mt][0] = __float_as_uint(sA[WIDX(m1,     k0)]);
                af[mt][1] = __float_as_uint(sA[WIDX(m1 + 8, k0)]);
                af[mt][2] = __float_as_uint(sA[WIDX(m1,     k0 + 4)]);
                af[mt][3] = __float_as_uint(sA[WIDX(m1 + 8, k0 + 4)]);
            }
            #pragma unroll
            for (int nt = 0; nt < NT; nt++) {
                int n1 = wn + nt * 8 + lm;
                bf[nt][0] = __float_as_uint(sB[WIDX(n1, k0)]);
                bf[nt][1] = __float_as_uint(sB[WIDX(n1, k0 + 4)]);
            }
            #pragma unroll
            for (int mt = 0; mt < MT; mt++)
                #pragma unroll
                for (int nt = 0; nt < NT; nt++)
                    MMA_TF32(acc[mt][nt], af[mt], bf[nt]);
        }
        if (more) {
            float* dA = sm + (stage ^ 1) * (ASZ + BSZ);
            float* dB = dA + ASZ;
            #pragma unroll
            for (int c = 0; c < 4; c++) {
                int k = ak + c * 8;
                *(float4*)&dA[(am * 32) + (((((k >> 2) & 7) ^ (am & 7))) << 2)] = aR[c];
            }
            #pragma unroll
            for (int c = 0; c < BCH; c++) {
                int k = bk + c * BST;
                *(float4*)&dB[(bn_ * 32) + (((((k >> 2) & 7) ^ (bn_ & 7))) << 2)] = bR[c];
            }
            __syncthreads();
            stage ^= 1;
        }
    }

    // ---- epilogue ----
    #pragma unroll
    for (int mt = 0; mt < MT; mt++) {
        int r0 = wm + mt * 16 + (lane >> 2);
        #pragma unroll
        for (int nt = 0; nt < NT; nt++) {
            int c0 = wn + nt * 8 + 2 * (lane & 3);
            float v0 = acc[mt][nt][0] * cscale, v1 = acc[mt][nt][1] * cscale;
            float v2 = acc[mt][nt][2] * cscale, v3 = acc[mt][nt][3] * cscale;
            if (doRound) { v0 = tf32r(v0); v1 = tf32r(v1); v2 = tf32r(v2); v3 = tf32r(v3); }
            if (bias) {
                float b0 = bias[c0], b1 = bias[c0 + 1];
                v0 += b0; v1 += b1; v2 += b0; v3 += b1;
            }
            *(float2*)&C[(size_t)r0 * ldc + c0]       = make_float2(v0, v1);
            *(float2*)&C[(size_t)(r0 + 8) * ldc + c0] = make_float2(v2, v3);
        }
    }
}

// ============================================================ LayerNorm (tf32-rounded out)
__global__ void ln_kernel(const float* __restrict__ x,
                          const float* __restrict__ gamma,
                          const float* __restrict__ beta) {
    int row = blockIdx.x;
    int t = threadIdx.x;
    const float4* xr = (const float4*)(x + (size_t)row * DIMC);
    float4 v = xr[t];
    float s = v.x + v.y + v.z + v.w;
    float q = v.x*v.x + v.y*v.y + v.z*v.z + v.w*v.w;
    __shared__ float s_sum[8], s_sq[8];
    #pragma unroll
    for (int o = 16; o > 0; o >>= 1) {
        s += __shfl_xor_sync(0xffffffffu, s, o);
        q += __shfl_xor_sync(0xffffffffu, q, o);
    }
    if ((t & 31) == 0) { s_sum[t >> 5] = s; s_sq[t >> 5] = q; }
    __syncthreads();
    if (t < 32) {
        float a = (t < 8) ? s_sum[t] : 0.f;
        float c = (t < 8) ? s_sq[t] : 0.f;
        #pragma unroll
        for (int o = 4; o > 0; o >>= 1) {
            a += __shfl_xor_sync(0xffffffffu, a, o);
            c += __shfl_xor_sync(0xffffffffu, c, o);
        }
        if (t == 0) { s_sum[0] = a; s_sq[0] = c; }
    }
    __syncthreads();
    float mean = s_sum[0] * (1.f / DIMC);
    float var  = s_sq[0] * (1.f / DIMC) - mean * mean;
    float rs = rsqrtf(var + 1e-5f);
    float4 gg = ((const float4*)gamma)[t];
    float4 bb = ((const float4*)beta)[t];
    float4 o;
    o.x = tf32r((v.x - mean) * rs * gg.x + bb.x);
    o.y = tf32r((v.y - mean) * rs * gg.y + bb.y);
    o.z = tf32r((v.z - mean) * rs * gg.z + bb.z);
    o.w = tf32r((v.w - mean) * rs * gg.w + bb.w);
    ((float4*)(g_xn + (size_t)row * DIMC))[t] = o;
}

// ============================================================ weight transpose + round
__global__ void wt_kernel(const float* __restrict__ src, float* __restrict__ dst,
                          int R, int C) {
    __shared__ float tile[32][33];
    int tx = threadIdx.x, ty = threadIdx.y;
    int c0 = blockIdx.x * 32, r0 = blockIdx.y * 32;
    #pragma unroll
    for (int i = 0; i < 32; i += 8)
        tile[ty + i][tx] = tf32r(src[(size_t)(r0 + ty + i) * C + c0 + tx]);
    __syncthreads();
    #pragma unroll
    for (int i = 0; i < 32; i += 8)
        dst[(size_t)(c0 + ty + i) * R + r0 + tx] = tile[tx][ty + i];
}

// V part of g_qkv -> g_vt[z][d][j]  (already rounded in proj epilogue)
__global__ void vt_kernel() {
    __shared__ float tile[32][33];
    int tx = threadIdx.x, ty = threadIdx.y;
    int z = blockIdx.z, b = z >> 4, g = z & 15;
    int d0 = blockIdx.x * 32, i0 = blockIdx.y * 32;
    const float* src = g_qkv + (size_t)b * SEQ * QKVC + 2048 + g * 64;
    #pragma unroll
    for (int i = 0; i < 32; i += 8)
        tile[ty + i][tx] = src[(size_t)(i0 + ty + i) * QKVC + d0 + tx];
    __syncthreads();
    float* dst = g_vt + (size_t)z * DH * SEQ;
    #pragma unroll
    for (int i = 0; i < 32; i += 8)
        dst[(size_t)(d0 + ty + i) * SEQ + i0 + tx] = tile[tx][ty + i];
}

// ============================================================ GEMM wrappers
__global__ __launch_bounds__(256) void proj_k() {
    int m0 = blockIdx.y * 128, cb = blockIdx.x * 128;
    const float* Bt = (cb < 1024) ? (g_wqt + (size_t)cb * DIMC)
                                  : (g_wkvt + (size_t)(cb - 1024) * DIMC);
    gemm_core<128, 4, false>(g_xn + (size_t)m0 * DIMC, DIMC, 0,
                             Bt, DIMC,
                             g_qkv + (size_t)m0 * QKVC + cb, QKVC, DIMC / 32,
                             (cb < 1024) ? 0.125f : 1.0f, 1, nullptr);
}

__global__ __launch_bounds__(256) void qk_k() {
    int z = blockIdx.z, b = z >> 4, h = z & 15;
    int m0 = blockIdx.y * 128, n0 = blockIdx.x * 128;
    const float* base = g_qkv + (size_t)b * SEQ * QKVC;
    gemm_core<128, 4, false>(base + (size_t)m0 * QKVC + h * DH, QKVC, 0,
                             base + (size_t)n0 * QKVC + 1024 + h * DH, QKVC,
                             g_dots + ((size_t)z * SEQ + m0) * SEQ + n0, SEQ, DH / 32,
                             1.0f, 0, nullptr);
}

__global__ __launch_bounds__(256) void av_k() {
    int z = blockIdx.y, m0 = blockIdx.x * 128;
    gemm_core<64, 2, false>(g_dots + (size_t)z * SEQ * SEQ + (size_t)m0 * SEQ, SEQ, 0,
                            g_vt + (size_t)z * DH * SEQ, SEQ,
                            g_ao + ((size_t)z * SEQ + m0) * DH, DH, SEQ / 32,
                            1.0f, 1, nullptr);
}

__global__ __launch_bounds__(256) void out_k(const float* __restrict__ bout,
                                             float* __restrict__ out) {
    int m0 = blockIdx.y * 128, n0 = blockIdx.x * 128;
    int b = m0 >> 11, i0 = m0 & (SEQ - 1);
    gemm_core<128, 4, true>(g_ao + ((size_t)(b * NH) * SEQ + i0) * DH, DH, SEQ * DH,
                            g_woutt + (size_t)n0 * DIMC, DIMC,
                            out + (size_t)m0 * DIMC + n0, DIMC, DIMC / 32,
                            1.0f, 0, bout + n0);
}

// ============================================================ pre-mix -> softmax -> post-mix (in place)
__global__ __launch_bounds__(256)
void mixsoftmax_kernel(const float* __restrict__ mix_pre, const float* __restrict__ mix_post) {
    extern __shared__ float srow[];          // [NH][SEQ]
    __shared__ float mp[256], mq[256];
    __shared__ float red[NH][8];
    __shared__ float mg[NH], linv[NH];
    int t = threadIdx.x;
    int b = blockIdx.x >> 11;
    int i = blockIdx.x & (SEQ - 1);
    mp[t] = mix_pre[t];
    mq[t] = mix_post[t];
    size_t base = ((size_t)(b * NH) * SEQ + i) * SEQ;
    for (int h = 0; h < NH; h++) {
        const float4* src = (const float4*)(g_dots + base + (size_t)h * SEQ * SEQ);
        float4* dst = (float4*)(srow + h * SEQ);
        for (int j = t; j < SEQ/4; j += 256) dst[j] = src[j];
    }
    __syncthreads();
    float tmax[NH];
    #pragma unroll
    for (int g = 0; g < NH; g++) tmax[g] = -3.4e38f;
    for (int j = t; j < SEQ; j += 256) {
        float sh[NH];
        #pragma unroll
        for (int h = 0; h < NH; h++) sh[h] = srow[h*SEQ + j];
        #pragma unroll
        for (int g = 0; g < NH; g++) {
            float v = 0.f;
            #pragma unroll
            for (int h = 0; h < NH; h++) v = fmaf(mp[h*NH + g], sh[h], v);
            srow[g*SEQ + j] = v;
            tmax[g] = fmaxf(tmax[g], v);
        }
    }
    int w = t >> 5, l = t & 31;
    #pragma unroll
    for (int g = 0; g < NH; g++) {
        float v = tmax[g];
        #pragma unroll
        for (int o = 16; o > 0; o >>= 1) v = fmaxf(v, __shfl_xor_sync(0xffffffffu, v, o));
        if (l == 0) red[g][w] = v;
    }
    __syncthreads();
    if (t < NH) {
        float v = red[t][0];
        #pragma unroll
        for (int w2 = 1; w2 < 8; w2++) v = fmaxf(v, red[t][w2]);
        mg[t] = v;
    }
    __syncthreads();
    float tsum[NH];
    #pragma unroll
    for (int g = 0; g < NH; g++) tsum[g] = 0.f;
    for (int j = t; j < SEQ; j += 256) {
        #pragma unroll
        for (int g = 0; g < NH; g++) {
            float e = __expf(srow[g*SEQ + j] - mg[g]);
            srow[g*SEQ + j] = e;
            tsum[g] += e;
        }
    }
    __syncthreads();
    #pragma unroll
    for (int g = 0; g < NH; g++) {
        float v = tsum[g];
        #pragma unroll
        for (int o = 16; o > 0; o >>= 1) v += __shfl_xor_sync(0xffffffffu, v, o);
        if (l == 0) red[g][w] = v;
    }
    __syncthreads();
    if (t < NH) {
        float v = 0.f;
        #pragma unroll
        for (int w2 = 0; w2 < 8; w2++) v += red[t][w2];
        linv[t] = 1.f / v;
    }
    __syncthreads();
    for (int j = t; j < SEQ; j += 256) {
        float ph[NH];
        #pragma unroll
        for (int h = 0; h < NH; h++) ph[h] = srow[h*SEQ + j] * linv[h];
        #pragma unroll
        for (int g = 0; g < NH; g++) {
            float v = 0.f;
            #pragma unroll
            for (int h = 0; h < NH; h++) v = fmaf(mq[h*NH + g], ph[h], v);
            g_dots[base + (size_t)g*SEQ*SEQ + j] = tf32r(v);
        }
    }
}

// ============================================================ launch
extern "C" void kernel_launch(void* const* d_in, const int* in_sizes, int n_in,
                              void* d_out, int out_size) {
    const float* x       = (const float*)d_in[0];
    const float* ln_g    = (const float*)d_in[1];
    const float* ln_b    = (const float*)d_in[2];
    const float* Wq      = (const float*)d_in[3];
    const float* Wkv     = (const float*)d_in[4];
    const float* mixpre  = (const float*)d_in[5];
    const float* mixpost = (const float*)d_in[6];
    const float* Wout    = (const float*)d_in[7];
    const float* bout    = (const float*)d_in[8];
    float* out = (float*)d_out;

    const int SM128 = 2 * (128*32 + 128*32) * 4;   // 65536
    const int SM64  = 2 * (128*32 +  64*32) * 4;   // 49152
    cudaFuncSetAttribute(mixsoftmax_kernel, cudaFuncAttributeMaxDynamicSharedMemorySize, NH * SEQ * 4);
    cudaFuncSetAttribute(proj_k, cudaFuncAttributeMaxDynamicSharedMemorySize, SM128);
    cudaFuncSetAttribute(qk_k,   cudaFuncAttributeMaxDynamicSharedMemorySize, SM128);
    cudaFuncSetAttribute(av_k,   cudaFuncAttributeMaxDynamicSharedMemorySize, SM64);
    cudaFuncSetAttribute(out_k,  cudaFuncAttributeMaxDynamicSharedMemorySize, SM128);

    float* d_wqt, *d_wkvt, *d_woutt;
    cudaGetSymbolAddress((void**)&d_wqt,   g_wqt);
    cudaGetSymbolAddress((void**)&d_wkvt,  g_wkvt);
    cudaGetSymbolAddress((void**)&d_woutt, g_woutt);

    dim3 tb(32, 8);
    ln_kernel<<<NROWS, 256>>>(x, ln_g, ln_b);
    wt_kernel<<<dim3(32, 32), tb>>>(Wq,   d_wqt,   DIMC, DIMC);
    wt_kernel<<<dim3(64, 32), tb>>>(Wkv,  d_wkvt,  DIMC, 2 * DIMC);
    wt_kernel<<<dim3(32, 32), tb>>>(Wout, d_woutt, DIMC, DIMC);
    proj_k<<<dim3(24, 32), 256, SM128>>>();
    vt_kernel<<<dim3(2, 64, 32), tb>>>();
    qk_k<<<dim3(16, 16, 32), 256, SM128>>>();
    mixsoftmax_kernel<<<BQ * SEQ, 256, NH * SEQ * 4>>>(mixpre, mixpost);
    av_k<<<dim3(16, 32), 256, SM64>>>();
    out_k<<<dim3(8, 32), 256, SM128>>>(bout, out);
}